// round 15
// baseline (speedup 1.0000x reference)
#include <cuda_runtime.h>
#include <cuda_bf16.h>

typedef unsigned short u16;
typedef unsigned int   u32;

#define BB    8
#define NN    4096
#define CC    64
#define CMID  128
#define NT    36                                   // upper-tri 8x8 tile count
#define KC1   8                                    // gemm1 split-K factor

// ---------------- static device scratch ----------------
__device__ float g_partial[512];
__device__ float g_M[CC*CC];                       // M = Wq @ Wk^T
__device__ float g_colpart[BB*64*CC];              // per-(b, nblk) colsums
__device__ float g_vbase[BB*CC];
__device__ float g_sp[CC];                         // s'[o] = sum_c W'[o][c]
__device__ float g_bp[CC];                         // b'[o] = Wl@b0 + bl
__device__ float g_gP[KC1*NT*CC*CC];               // G partials [kc][tile][64x64]
__device__ __align__(16) u16 Zn[NN*512];           // bf16 x, [n][b*64+c]
__device__ __align__(16) u16 Zt[512*NN];           // bf16 x, [b*64+c][n]
__device__ __align__(16) u16 g_Dt[BB*64*512];      // per b: D^T rows [c][k]

__device__ __forceinline__ u32 f2bf(float f) {
    return (u32)__bfloat16_as_ushort(__float2bfloat16(f));
}
__device__ __forceinline__ float bf2f(u16 v) {
    return __bfloat162float(__ushort_as_bfloat16(v));
}

// upper-tri tile index for a<=b
__device__ __forceinline__ int tix(int a, int b) {
    return a*8 - (a*(a-1))/2 + (b - a);
}

// mma.sync m16n8k16 bf16, row.col, f32 accum
#define MMA_16816(d, a, b)                                             \
    asm volatile(                                                      \
        "mma.sync.aligned.m16n8k16.row.col.f32.bf16.bf16.f32 "         \
        "{%0,%1,%2,%3}, {%4,%5,%6,%7}, {%8,%9}, {%0,%1,%2,%3};\n"      \
        : "+f"(d[0]), "+f"(d[1]), "+f"(d[2]), "+f"(d[3])               \
        : "r"(a[0]), "r"(a[1]), "r"(a[2]), "r"(a[3]),                  \
          "r"(b[0]), "r"(b[1]))

#define LDSM_X4(r0, r1, r2, r3, addr)                                  \
    asm volatile("ldmatrix.sync.aligned.m8n8.x4.shared.b16 "           \
                 "{%0,%1,%2,%3}, [%4];"                                \
                 : "=r"(r0), "=r"(r1), "=r"(r2), "=r"(r3) : "r"(addr))

#define CP_ASYNC16(dst, src)                                           \
    asm volatile("cp.async.cg.shared.global [%0], [%1], 16;"           \
                 :: "r"(dst), "l"(src))

// ---------------- K1: stats + bf16 convert + transpose + M + s'/b' -----------
// grid 529: 0-511 stats; 512-527 M; 528 s'/b'
__global__ void k1_stats(const float* __restrict__ x,
                         const float* __restrict__ Wq,
                         const float* __restrict__ Wk,
                         const float* __restrict__ Wl,
                         const float* __restrict__ bl,
                         const float* __restrict__ g0,
                         const float* __restrict__ b0) {
    __shared__ float xs[64][68];
    __shared__ float red[256];
    int t = threadIdx.x;
    int bx = blockIdx.x;

    if (bx == 528) {
        if (t < CC) {
            float sp = 0.f, bp = 0.f;
            #pragma unroll 8
            for (int c = 0; c < CC; c++) {
                float w = Wl[t*CC + c];
                sp = fmaf(w, g0[c], sp);
                bp = fmaf(w, b0[c], bp);
            }
            g_sp[t] = sp;
            g_bp[t] = bp + bl[t];
        }
        return;
    }
    if (bx >= 512) {
        int e = (bx - 512) * 256 + t;
        int c  = e >> 6;
        int c2 = e & 63;
        const float* q = Wq + c  * CMID;
        const float* k = Wk + c2 * CMID;
        float acc = 0.f;
        #pragma unroll 8
        for (int m = 0; m < CMID; m++) acc = fmaf(q[m], k[m], acc);
        g_M[e] = acc;
        return;
    }

    int b = bx >> 6, nblk = bx & 63, n0 = nblk * 64;
    const float* xp = x + (((b << 12) + n0) << 6);

    float ss = 0.f;
    #pragma unroll
    for (int i = 0; i < 4; i++) {
        int item = t + (i << 8);
        int r = item >> 4, c4 = (item & 15) << 2;
        float4 v = *(const float4*)(xp + (r << 6) + c4);
        *(float4*)&xs[r][c4] = v;
        ss += v.x*v.x + v.y*v.y + v.z*v.z + v.w*v.w;
        // Zn written directly from registers (no smem round trip)
        u32 z0 = f2bf(v.x) | (f2bf(v.y) << 16);
        u32 z1 = f2bf(v.z) | (f2bf(v.w) << 16);
        *(uint2*)&Zn[(n0 + r)*512 + b*64 + c4] = make_uint2(z0, z1);
    }
    red[t] = ss;
    __syncthreads();
    for (int s = 128; s > 0; s >>= 1) {
        if (t < s) red[t] += red[t + s];
        __syncthreads();
    }
    if (t == 0) g_partial[bx] = red[0];

    if (t < 64) {
        float s = 0.f;
        #pragma unroll 8
        for (int n = 0; n < 64; n++) s += xs[n][t];
        g_colpart[(b*64 + nblk)*CC + t] = s;
    }

    // Zt write, coalesced: lanes 0-3 cover one contiguous 128B row segment
    {
        int c = t >> 2, nq4 = (t & 3) << 4;
        u32 p[8];
        #pragma unroll
        for (int q = 0; q < 8; q++)
            p[q] = f2bf(xs[nq4 + 2*q][c]) | (f2bf(xs[nq4 + 2*q + 1][c]) << 16);
        u16* dst = Zt + (b*64 + c)*NN + n0 + nq4;
        *(uint4*)dst       = make_uint4(p[0], p[1], p[2], p[3]);
        *(uint4*)(dst + 8) = make_uint4(p[4], p[5], p[6], p[7]);
    }
}

// ---------------- K3: GEMM1  G = Z^T Z, upper-tri, pipelined -----------------
// grid (36 tiles, 8 kchunks); block 256 = 8 warps (2x4), warp tile 32x16
__global__ void __launch_bounds__(256) k_gemm1() {
    __shared__ __align__(16) u16 buf[2][2][64][72];   // [stage][A/B] 36864 B
    int t = threadIdx.x, w = t >> 5, lane = t & 31;
    int g = lane >> 2, tq = lane & 3;
    int kc = blockIdx.y;
    int ti = 0, rem = blockIdx.x;
    while (rem > 7 - ti) { rem -= 8 - ti; ti++; }
    int tj = ti + rem;
    int wr = w & 1, wc = w >> 1;

    u32 smem_base = (u32)__cvta_generic_to_shared(&buf[0][0][0][0]);

    const u16* ZtA = Zt + (ti*64)*NN + kc*512;
    const u16* ZtB = Zt + (tj*64)*NN + kc*512;

    int a_row_l = lane & 15;
    int a_col_l = (lane >> 4) << 3;
    int b_row_l = (lane & 7) + ((lane >> 4) << 3);
    int b_col_l = ((lane >> 3) & 1) << 3;

    auto issue = [&](int step, int s) {
        u32 a_b = smem_base + (u32)s*18432;
        u32 b_b = a_b + 9216;
        int n0 = step * 64;
        #pragma unroll
        for (int i = 0; i < 2; i++) {
            int item = t + (i << 8);
            int r = item >> 3, c8 = (item & 7) << 3;
            CP_ASYNC16(a_b + (u32)(r*72 + c8)*2, ZtA + r*NN + n0 + c8);
            CP_ASYNC16(b_b + (u32)(r*72 + c8)*2, ZtB + r*NN + n0 + c8);
        }
        asm volatile("cp.async.commit_group;");
    };

    float acc[2][2][4];
    #pragma unroll
    for (int a = 0; a < 2; a++)
        #pragma unroll
        for (int c = 0; c < 2; c++)
            #pragma unroll
            for (int d = 0; d < 4; d++) acc[a][c][d] = 0.f;

    issue(0, 0);

    for (int step = 0; step < 8; step++) {
        int s = step & 1;
        asm volatile("cp.async.wait_group 0;");
        __syncthreads();
        if (step < 7) issue(step + 1, s ^ 1);

        u32 a_b = smem_base + (u32)s*18432;
        u32 b_b = a_b + 9216;
        #pragma unroll
        for (int ks = 0; ks < 4; ks++) {
            int k16 = ks * 16;
            u32 a[2][4], bf[2][2];
            #pragma unroll
            for (int mi = 0; mi < 2; mi++) {
                int m = wr*32 + mi*16 + a_row_l;
                u32 addr = a_b + (u32)(m*72 + k16 + a_col_l)*2;
                LDSM_X4(a[mi][0], a[mi][1], a[mi][2], a[mi][3], addr);
            }
            {
                int n = wc*16 + b_row_l;
                u32 addr = b_b + (u32)(n*72 + k16 + b_col_l)*2;
                LDSM_X4(bf[0][0], bf[0][1], bf[1][0], bf[1][1], addr);
            }
            #pragma unroll
            for (int mi = 0; mi < 2; mi++)
                #pragma unroll
                for (int ni = 0; ni < 2; ni++)
                    MMA_16816(acc[mi][ni], a[mi], bf[ni]);
        }
    }

    float* gp = g_gP + (kc*NT + blockIdx.x)*4096;
    #pragma unroll
    for (int mi = 0; mi < 2; mi++)
        #pragma unroll
        for (int ni = 0; ni < 2; ni++) {
            int i0 = wr*32 + mi*16 + g;
            int j0 = wc*16 + ni*8 + 2*tq;
            *(float2*)(gp + i0*64 + j0)     = make_float2(acc[mi][ni][0], acc[mi][ni][1]);
            *(float2*)(gp + (i0+8)*64 + j0) = make_float2(acc[mi][ni][2], acc[mi][ni][3]);
        }
}

// sum the KC1 split-K partials for one element
__device__ __forceinline__ float gsum8(int ga) {
    float v = 0.f;
    #pragma unroll
    for (int kk = 0; kk < KC1; kk++) v += g_gP[kk*NT*4096 + ga];
    return v;
}

// ---------------- K4: D^T slices only ----------------------------------------
// grid 256: pair = bx>>2, 16-col slice q = bx&3
__global__ void __launch_bounds__(256) k_DE() {
    __shared__ float Mt[64][68];     // Mt[j][kp] = M[kp][j]
    __shared__ float Gb[64][68];     // Gb[j][cl]
    __shared__ float red[256];
    __shared__ float s_scal;
    int t = threadIdx.x;
    int bx = blockIdx.x;
    int pair = bx >> 2, q = bx & 3;
    int b1 = pair >> 3, b2 = pair & 7;
    bool tr = (b1 > b2);
    int tile = tr ? tix(b2, b1) : tix(b1, b2);

    red[t] = g_partial[t] + g_partial[t + 256];
    __syncthreads();
    for (int s = 128; s > 0; s >>= 1) {
        if (t < s) red[t] += red[t + s];
        __syncthreads();
    }
    if (t == 0) s_scal = (float)(1.0 / sqrt(sqrt((double)red[0])));

    #pragma unroll
    for (int i = 0; i < 16; i++) {
        int e = t + (i << 8);
        Mt[e & 63][e >> 6] = g_M[e];
    }

    int c0 = q * 16;
    if (!tr) {
        #pragma unroll
        for (int i = 0; i < 4; i++) {
            int e = t + (i << 8);
            int j = e >> 4, cl = e & 15;
            Gb[j][cl] = gsum8(tile*4096 + j*64 + c0 + cl);
        }
    } else {
        #pragma unroll
        for (int i = 0; i < 4; i++) {
            int e = t + (i << 8);
            int cl = e >> 6, j = e & 63;
            Gb[j][cl] = gsum8(tile*4096 + (c0 + cl)*64 + j);
        }
    }
    __syncthreads();

    float coeff = s_scal * 0.125f * ((b1 == b2) ? 0.875f : -0.125f);
    int cl = t >> 4, c = c0 + cl;
    int kp4 = (t & 15) << 2;
    float d0 = 0.f, d1 = 0.f, d2 = 0.f, d3 = 0.f;
    #pragma unroll
    for (int j = 0; j < 64; j++) {
        float gv = Gb[j][cl];
        float4 m = *(const float4*)&Mt[j][kp4];
        d0 = fmaf(m.x, gv, d0);
        d1 = fmaf(m.y, gv, d1);
        d2 = fmaf(m.z, gv, d2);
        d3 = fmaf(m.w, gv, d3);
    }
    d0 *= coeff; d1 *= coeff; d2 *= coeff; d3 *= coeff;
    u32 p0 = f2bf(d0) | (f2bf(d1) << 16);
    u32 p1 = f2bf(d2) | (f2bf(d3) << 16);
    *(uint2*)&g_Dt[(b2*64 + c)*512 + b1*64 + kp4] = make_uint2(p0, p1);

    if (q == 3 && pair < 8 && t < 64) {
        float s = 0.f;
        #pragma unroll 8
        for (int k = 0; k < 64; k++) s += g_colpart[(pair*64 + k)*CC + t];
        g_vbase[pair*CC + t] = s * 0.125f;
    }
}

// ---------------- K5: GEMM2  P = Z@D; U = ub + P@W'^T; slim epilogue ---------
// grid (32, 8); block 256 = 8 warps (4x2 mainloop); 128-row tile
// smem: [0,55296) stage buffers (A 128x72 + B 64x72 u16 per stage)
//   post-loop overlap: Pb u16 128x72 @0 (18432); ut f32 128x68 @18432 (34816)
//   Wp u16 64x72 @55296 (9216); pars @64512 (1536). Total 66048 -> 3 CTAs/SM
#define G2_SMEM 66048
__global__ void __launch_bounds__(256) k_gemm2(
        const float* __restrict__ Wl, const float* __restrict__ g0,
        const float* __restrict__ g1, const float* __restrict__ b1v,
        float* __restrict__ out) {
    extern __shared__ char smraw[];
    u16*   Pb       = (u16*)smraw;                          // bf16 P_corr
    float (*ut)[68] = (float(*)[68])(smraw + 18432);
    u16*   Wp       = (u16*)(smraw + 55296);
    float* pars     = (float*)(smraw + 64512);              // 384 floats
    u32 smem_base   = (u32)__cvta_generic_to_shared(smraw);
    u32 pb_base     = smem_base;
    u32 wp_base     = smem_base + 55296;

    int t = threadIdx.x, w = t >> 5, lane = t & 31;
    int g = lane >> 2, tq = lane & 3;
    int n0 = blockIdx.x * 128, b = blockIdx.y;
    int wr = w & 3, wc = w >> 2;

    // W' = Wl*g0 -> bf16 smem [o][72]; pars incl ub and vbase
    #pragma unroll
    for (int i = 0; i < 16; i++) {
        int e = t + (i << 8);
        int o = e >> 6, c = e & 63;
        Wp[o*72 + c] = (u16)f2bf(Wl[e] * g0[c]);
    }
    if (t < 64) {
        pars[t]       = g_sp[t];
        pars[64 + t]  = g_bp[t];
        pars[128 + t] = g1[t];
        pars[192 + t] = b1v[t];
        float vb = g_vbase[b*CC + t];
        pars[320 + t] = vb;
        float s = 0.f;
        #pragma unroll 8
        for (int c = 0; c < 64; c++)
            s = fmaf(g_vbase[b*CC + c], Wl[t*CC + c] * g0[c], s);
        pars[256 + t] = s;
    }

    const u16* Zrow = Zn + n0*512;
    const u16* Drow = g_Dt + b*64*512;

    int a_row_l = lane & 15;
    int a_col_l = (lane >> 4) << 3;
    int b_row_l = (lane & 7) + ((lane >> 4) << 3);
    int b_col_l = ((lane >> 3) & 1) << 3;

    auto issue = [&](int kc, int s) {
        u32 as_b = smem_base + (u32)s*27648;
        u32 bs_b = as_b + 18432;
        int k0 = kc * 64;
        #pragma unroll
        for (int i = 0; i < 4; i++) {          // A: 128x64 u16
            int item = t + (i << 8);
            int r = item >> 3, c8 = (item & 7) << 3;
            CP_ASYNC16(as_b + (u32)(r*72 + c8)*2, Zrow + r*512 + k0 + c8);
        }
        #pragma unroll
        for (int i = 0; i < 2; i++) {          // B: 64x64 u16
            int item = t + (i << 8);
            int r = item >> 3, c8 = (item & 7) << 3;
            CP_ASYNC16(bs_b + (u32)(r*72 + c8)*2, Drow + r*512 + k0 + c8);
        }
        asm volatile("cp.async.commit_group;");
    };

    float acc[2][4][4];
    #pragma unroll
    for (int a = 0; a < 2; a++)
        #pragma unroll
        for (int c = 0; c < 4; c++)
            #pragma unroll
            for (int d = 0; d < 4; d++) acc[a][c][d] = 0.f;

    issue(0, 0);

    for (int kc = 0; kc < 8; kc++) {
        int s = kc & 1;
        asm volatile("cp.async.wait_group 0;");
        __syncthreads();
        if (kc < 7) issue(kc + 1, s ^ 1);

        u32 as_b = smem_base + (u32)s*27648;
        u32 bs_b = as_b + 18432;
        #pragma unroll
        for (int ks = 0; ks < 4; ks++) {
            int k16 = ks * 16;
            u32 a[2][4], bf[4][2];
            #pragma unroll
            for (int mi = 0; mi < 2; mi++) {
                int m = wr*32 + mi*16 + a_row_l;
                u32 addr = as_b + (u32)(m*72 + k16 + a_col_l)*2;
                LDSM_X4(a[mi][0], a[mi][1], a[mi][2], a[mi][3], addr);
            }
            #pragma unroll
            for (int np = 0; np < 2; np++) {
                int n = wc*32 + np*16 + b_row_l;
                u32 addr = bs_b + (u32)(n*72 + k16 + b_col_l)*2;
                LDSM_X4(bf[np*2][0], bf[np*2][1], bf[np*2+1][0], bf[np*2+1][1], addr);
            }
            #pragma unroll
            for (int mi = 0; mi < 2; mi++)
                #pragma unroll
                for (int ni = 0; ni < 4; ni++)
                    MMA_16816(acc[mi][ni], a[mi], bf[ni]);
        }
    }
    __syncthreads();   // all mma reads done -> Pb may overwrite buffer 0

    // write Pb = bf16(P_corr)
    #pragma unroll
    for (int mi = 0; mi < 2; mi++)
        #pragma unroll
        for (int ni = 0; ni < 4; ni++) {
            int r = wr*32 + mi*16 + g;
            int c = wc*32 + ni*8 + 2*tq;
            *(u32*)&Pb[r*72 + c]       = f2bf(acc[mi][ni][0]) | (f2bf(acc[mi][ni][1]) << 16);
            *(u32*)&Pb[(r + 8)*72 + c] = f2bf(acc[mi][ni][2]) | (f2bf(acc[mi][ni][3]) << 16);
        }
    __syncthreads();

    // stage 2: U_corr = P_corr @ W'^T (K=64); warp w handles rows w*16..+15
    float accU[8][4];
    #pragma unroll
    for (int c = 0; c < 8; c++)
        #pragma unroll
        for (int d = 0; d < 4; d++) accU[c][d] = 0.f;

    #pragma unroll
    for (int ks = 0; ks < 4; ks++) {
        int k16 = ks * 16;
        u32 a2[4], bW[8][2];
        {
            int m = w*16 + a_row_l;
            u32 addr = pb_base + (u32)(m*72 + k16 + a_col_l)*2;
            LDSM_X4(a2[0], a2[1], a2[2], a2[3], addr);
        }
        #pragma unroll
        for (int np = 0; np < 4; np++) {
            int n = np*16 + b_row_l;
            u32 addr = wp_base + (u32)(n*72 + k16 + b_col_l)*2;
            LDSM_X4(bW[np*2][0], bW[np*2][1], bW[np*2+1][0], bW[np*2+1][1], addr);
        }
        #pragma unroll
        for (int ni = 0; ni < 8; ni++)
            MMA_16816(accU[ni], a2, bW[ni]);
    }

    // ut = U_corr + ub  (overlaps dead stage buffer 1; after syncs above)
    #pragma unroll
    for (int ni = 0; ni < 8; ni++) {
        int r = w*16 + g;
        int c = ni*8 + 2*tq;
        float2 ub = *(const float2*)&pars[256 + c];
        *(float2*)&ut[r][c]     = make_float2(accU[ni][0] + ub.x, accU[ni][1] + ub.y);
        *(float2*)&ut[r + 8][c] = make_float2(accU[ni][2] + ub.x, accU[ni][3] + ub.y);
    }
    __syncthreads();

    // epilogue: v = vbase + float(Pb); 2 rows/iter, one-pass variance
    float sp0 = pars[lane],       sp1 = pars[lane + 32];
    float bp0 = pars[64 + lane],  bp1 = pars[64 + lane + 32];
    float gg0 = pars[128 + lane], gg1 = pars[128 + lane + 32];
    float be0 = pars[192 + lane], be1 = pars[192 + lane + 32];
    float vb0 = pars[320 + lane], vb1 = pars[320 + lane + 32];
    for (int rr = 0; rr < 16; rr += 2) {
        int ra = w*16 + rr, rb = ra + 1;
        float av0 = bf2f(Pb[ra*72 + lane])      + vb0;
        float av1 = bf2f(Pb[ra*72 + lane + 32]) + vb1;
        float bv0 = bf2f(Pb[rb*72 + lane])      + vb0;
        float bv1 = bf2f(Pb[rb*72 + lane + 32]) + vb1;
        float aS = av0 + av1, aQ = fmaf(av0, av0, av1*av1);
        float bS = bv0 + bv1, bQ = fmaf(bv0, bv0, bv1*bv1);
        #pragma unroll
        for (int o = 16; o > 0; o >>= 1) {
            aS += __shfl_xor_sync(0xffffffffu, aS, o);
            aQ += __shfl_xor_sync(0xffffffffu, aQ, o);
            bS += __shfl_xor_sync(0xffffffffu, bS, o);
            bQ += __shfl_xor_sync(0xffffffffu, bQ, o);
        }
        float amu = aS * (1.f/64.f), bmu = bS * (1.f/64.f);
        float ars = rsqrtf(aQ*(1.f/64.f) - amu*amu + 1e-5f);
        float brs = rsqrtf(bQ*(1.f/64.f) - bmu*bmu + 1e-5f);

        float au0 = ut[ra][lane], au1 = ut[ra][lane + 32];
        float bu0 = ut[rb][lane], bu1 = ut[rb][lane + 32];
        float aa0 = ars * (au0 - amu*sp0) + bp0;
        float aa1 = ars * (au1 - amu*sp1) + bp1;
        float ba0 = brs * (bu0 - bmu*sp0) + bp0;
        float ba1 = brs * (bu1 - bmu*sp1) + bp1;

        float ga0 = 0.5f*aa0*(1.f + erff(aa0*0.7071067811865476f));
        float ga1 = 0.5f*aa1*(1.f + erff(aa1*0.7071067811865476f));
        float gb0 = 0.5f*ba0*(1.f + erff(ba0*0.7071067811865476f));
        float gb1 = 0.5f*ba1*(1.f + erff(ba1*0.7071067811865476f));

        float aS2 = ga0 + ga1, aQ2 = fmaf(ga0, ga0, ga1*ga1);
        float bS2 = gb0 + gb1, bQ2 = fmaf(gb0, gb0, gb1*gb1);
        #pragma unroll
        for (int o = 16; o > 0; o >>= 1) {
            aS2 += __shfl_xor_sync(0xffffffffu, aS2, o);
            aQ2 += __shfl_xor_sync(0xffffffffu, aQ2, o);
            bS2 += __shfl_xor_sync(0xffffffffu, bS2, o);
            bQ2 += __shfl_xor_sync(0xffffffffu, bQ2, o);
        }
        float amu2 = aS2 * (1.f/64.f), bmu2 = bS2 * (1.f/64.f);
        float ars2 = rsqrtf(aQ2*(1.f/64.f) - amu2*amu2 + 1e-5f);
        float brs2 = rsqrtf(bQ2*(1.f/64.f) - bmu2*bmu2 + 1e-5f);

        float* opa = out + (((b << 12) + n0 + ra) << 6);
        float* opb = out + (((b << 12) + n0 + rb) << 6);
        opa[lane]      = (ga0 - amu2)*ars2*gg0 + be0;
        opa[lane + 32] = (ga1 - amu2)*ars2*gg1 + be1;
        opb[lane]      = (gb0 - bmu2)*brs2*gg0 + be0;
        opb[lane + 32] = (gb1 - bmu2)*brs2*gg1 + be1;
    }
}

// ----------------------------------------------------------------------------
extern "C" void kernel_launch(void* const* d_in, const int* in_sizes, int n_in,
                              void* d_out, int out_size) {
    const float* x  = (const float*)d_in[0];
    const float* Wq = (const float*)d_in[1];
    const float* Wk = (const float*)d_in[2];
    const float* Wl = (const float*)d_in[3];
    const float* bl = (const float*)d_in[4];
    const float* g0 = (const float*)d_in[5];
    const float* b0 = (const float*)d_in[6];
    const float* g1 = (const float*)d_in[7];
    const float* b1 = (const float*)d_in[8];
    float* out = (float*)d_out;

    cudaFuncSetAttribute(k_gemm2, cudaFuncAttributeMaxDynamicSharedMemorySize,
                         G2_SMEM);

    k1_stats<<<529, 256>>>(x, Wq, Wk, Wl, bl, g0, b0);
    k_gemm1 <<<dim3(NT, KC1), 256>>>();
    k_DE    <<<256, 256>>>();
    k_gemm2 <<<dim3(32, 8), 256, G2_SMEM>>>(Wl, g0, g1, b1, out);
}